// round 15
// baseline (speedup 1.0000x reference)
#include <cuda_runtime.h>
#include <cuda_bf16.h>
#include <cstdint>
#include <math.h>

// Problem constants
#define B_  64
#define T_  1024
#define I_  128
#define H_  256
#define NT  (B_ * T_)          // 65536 rows

typedef unsigned long long u64;

// ---------------------------------------------------------------------------
// Static device scratch (no runtime allocation allowed)
// ---------------------------------------------------------------------------
__device__ float2 g_Z[(size_t)NT * H_];        // {zf, zc} x-part (+bias), 128 MB
__device__ float  g_y1[(size_t)NT * H_];       // layer-1 outputs, 64 MB
__device__ u64    g_Wh[2][H_ * H_];            // recurrent weights {wf,wc} packed, k-major

// ---------------------------------------------------------------------------
// f32x2 + PTX helpers
// ---------------------------------------------------------------------------
__device__ __forceinline__ u64 pack2(float x, float y) {
    u64 r;
    asm("mov.b64 %0, {%1, %2};" : "=l"(r) : "f"(x), "f"(y));
    return r;
}
__device__ __forceinline__ void unpack2(u64 v, float& x, float& y) {
    asm("mov.b64 {%0, %1}, %2;" : "=f"(x), "=f"(y) : "l"(v));
}
__device__ __forceinline__ void ffma2(u64& d, u64 a, u64 b) {
    asm("fma.rn.f32x2 %0, %1, %2, %0;" : "+l"(d) : "l"(a), "l"(b));
}
__device__ __forceinline__ u64 fadd2(u64 a, u64 b) {
    u64 d;
    asm("add.rn.f32x2 %0, %1, %2;" : "=l"(d) : "l"(a), "l"(b));
    return d;
}
__device__ __forceinline__ float tanh_fast(float x) {   // MUFU.TANH
    float y;
    asm("tanh.approx.f32 %0, %1;" : "=f"(y) : "f"(x));
    return y;
}
__device__ __forceinline__ uint32_t smem_u32(const void* p) {
    uint32_t a;
    asm("{ .reg .u64 t; cvta.to.shared.u64 t, %1; cvt.u32.u64 %0, t; }"
        : "=r"(a) : "l"(p));
    return a;
}
__device__ __forceinline__ uint32_t cluster_rank() {
    uint32_t r;
    asm("mov.u32 %0, %%cluster_ctarank;" : "=r"(r));
    return r;
}
__device__ __forceinline__ uint32_t mapa_u32(uint32_t addr, uint32_t rank) {
    uint32_t r;
    asm("mapa.shared::cluster.u32 %0, %1, %2;" : "=r"(r) : "r"(addr), "r"(rank));
    return r;
}
__device__ __forceinline__ void cluster_arrive() {
    asm volatile("barrier.cluster.arrive.aligned;" ::: "memory");
}
__device__ __forceinline__ void cluster_wait() {
    asm volatile("barrier.cluster.wait.aligned;" ::: "memory");
}
__device__ __forceinline__ void mbar_init(uint32_t addr, uint32_t count) {
    asm volatile("mbarrier.init.shared.b64 [%0], %1;" :: "r"(addr), "r"(count) : "memory");
}
__device__ __forceinline__ void mbar_arrive_expect_tx(uint32_t addr, uint32_t bytes) {
    asm volatile("mbarrier.arrive.expect_tx.shared.b64 _, [%0], %1;"
                 :: "r"(addr), "r"(bytes) : "memory");
}
// Async remote store, HW-tracked completion at the destination's mbarrier.
__device__ __forceinline__ void st_async_u64(uint32_t raddr, u64 v, uint32_t rmbar) {
    asm volatile("st.async.shared::cluster.mbarrier::complete_tx::bytes.u64 [%0], %1, [%2];"
                 :: "r"(raddr), "l"(v), "r"(rmbar) : "memory");
}
__device__ __forceinline__ void mbar_wait_cluster(uint32_t addr, uint32_t parity) {
    uint32_t done;
    asm volatile(
        "{\n\t"
        ".reg .pred p;\n\t"
        "mbarrier.try_wait.parity.acquire.cluster.shared::cta.b64 p, [%1], %2;\n\t"
        "selp.b32 %0, 1, 0, p;\n\t"
        "}"
        : "=r"(done) : "r"(addr), "r"(parity) : "memory");
    if (!done) {
        asm volatile(
            "{\n\t"
            ".reg .pred P1;\n\t"
            "WAIT_LOOP_%=:\n\t"
            "mbarrier.try_wait.parity.acquire.cluster.shared::cta.b64 P1, [%0], %1, 0x989680;\n\t"
            "@P1 bra.uni WAIT_DONE_%=;\n\t"
            "bra.uni WAIT_LOOP_%=;\n\t"
            "WAIT_DONE_%=:\n\t"
            "}"
            :: "r"(addr), "r"(parity) : "memory");
    }
}

// ---------------------------------------------------------------------------
// Repack recurrent weight rows: g_Wh[layer][k*H + j] = pack{Wf[D+k][j], Wc[D+k][j]}
// ---------------------------------------------------------------------------
__global__ void repack_wh(const float* __restrict__ Wf, const float* __restrict__ Wc,
                          int D, int layer)
{
    int j = threadIdx.x;
    int k = blockIdx.x;
    float wf = Wf[(size_t)(D + k) * H_ + j];
    float wc = Wc[(size_t)(D + k) * H_ + j];
    g_Wh[layer][k * H_ + j] = pack2(wf, wc);
}

// ---------------------------------------------------------------------------
// Precompute x-part of both gates (unchanged, passing since round 6):
//   g_Z[n][j] = { bf[j] + sum_d X[n][d]*Wf[d][j],  bc[j] + sum_d X[n][d]*Wc[d][j] }
// ---------------------------------------------------------------------------
__global__ void __launch_bounds__(256) gemm_x(
    const float* __restrict__ Xext, int D, int useY1,
    const float* __restrict__ Wf, const float* __restrict__ Wc,
    const float* __restrict__ bf, const float* __restrict__ bc)
{
    const float* __restrict__ X = useY1 ? (const float*)g_y1 : Xext;

    __shared__ float2 Xs[16][130];   // x splatted {x,x}
    __shared__ float2 Ws[16][34];    // {wf,wc}

    const int tid = threadIdx.x;
    const int tx  = tid & 15;
    const int ty  = tid >> 4;
    const int n0  = blockIdx.x * 128;
    const int j0  = blockIdx.y * 32;
    const int jj  = j0 + 2 * tx;

    u64 acc[8][2];
    {
        u64 bi0 = pack2(bf[jj],     bc[jj]);
        u64 bi1 = pack2(bf[jj + 1], bc[jj + 1]);
#pragma unroll
        for (int r = 0; r < 8; r++) { acc[r][0] = bi0; acc[r][1] = bi1; }
    }

    for (int d0 = 0; d0 < D; d0 += 16) {
        __syncthreads();
        {
            int r  = tid >> 2;
            int c4 = (tid & 3) * 4;
#pragma unroll
            for (int rr = 0; rr < 2; rr++) {
                int row = r + rr * 64;
                float4 v = *(const float4*)&X[(size_t)(n0 + row) * D + d0 + c4];
                Xs[c4 + 0][row] = make_float2(v.x, v.x);
                Xs[c4 + 1][row] = make_float2(v.y, v.y);
                Xs[c4 + 2][row] = make_float2(v.z, v.z);
                Xs[c4 + 3][row] = make_float2(v.w, v.w);
            }
        }
        for (int e = tid; e < 512; e += 256) {
            int k = e >> 5, jw = e & 31;
            Ws[k][jw] = make_float2(Wf[(size_t)(d0 + k) * H_ + j0 + jw],
                                    Wc[(size_t)(d0 + k) * H_ + j0 + jw]);
        }
        __syncthreads();

#pragma unroll
        for (int kk = 0; kk < 16; kk++) {
            ulonglong2 wq = *(const ulonglong2*)&Ws[kk][2 * tx];
            const ulonglong2* xp = (const ulonglong2*)&Xs[kk][ty * 8];
#pragma unroll
            for (int q = 0; q < 4; q++) {
                ulonglong2 xq = xp[q];
                ffma2(acc[2 * q + 0][0], xq.x, wq.x);
                ffma2(acc[2 * q + 0][1], xq.x, wq.y);
                ffma2(acc[2 * q + 1][0], xq.y, wq.x);
                ffma2(acc[2 * q + 1][1], xq.y, wq.y);
            }
        }
    }

#pragma unroll
    for (int r = 0; r < 8; r++) {
        int n = n0 + ty * 8 + r;
        float4 v;
        unpack2(acc[r][0], v.x, v.y);
        unpack2(acc[r][1], v.z, v.w);
        *(float4*)&g_Z[(size_t)n * H_ + jj] = v;
    }
}

// ---------------------------------------------------------------------------
// Recurrence v8: PARTIAL-SUM exchange instead of h broadcast.
// Cluster of 4 CTAs; CTA r owns columns [64r,64r+64) AND k-slice [64r,64r+64).
// The k-slice's h values are exactly the columns this CTA produced last step,
// so the k-loop needs NO peer data: it starts right after the local epilogue.
// 256 threads: thread = global column (0..255); accumulates its column over
// the CTA's 64 own-k, both batches (weights in 64 regs, h local broadcast).
// After the k-loop each thread fires its 2 partial u64s (batch 0/1, lanes
// {f,c}) to the column-owner CTA via st.async + tx mbarrier; owner waits,
// reduces 4 partials, applies gates, stores h LOCALLY. Cross-CTA wait now
// overlaps peers' k-loops instead of serializing before them.
// ---------------------------------------------------------------------------
#define STEP_TX_BYTES 4096u   // 4 src CTAs x 64 cols x 2 batches x 8B

__global__ void __cluster_dims__(4, 1, 1) __launch_bounds__(256, 1)
mgu_recur8(int layer, float* __restrict__ Yext, float* __restrict__ Hfin)
{
    __shared__ __align__(16) u64 hbuf[2][2][64];    // [parity][batch][own k] {h,h}
    __shared__ __align__(16) u64 pbuf[2][64][2][4]; // [parity][own col][batch][src]
    __shared__ __align__(8)  u64 mbars[2];          // per-parity tx mbarrier

    const int tid = threadIdx.x;                    // = global column 0..255
    const uint32_t rank = cluster_rank();           // own col-block AND k-slice
    const int c   = blockIdx.x >> 2;                // cluster id -> batch pair
    const int b0  = 2 * c;
    const int destRank = tid >> 6;                  // owner CTA of this column
    const int lc       = tid & 63;                  // local col index at owner

    const u64* __restrict__ Whg = g_Wh[layer];
    float* __restrict__ Y = (layer == 0) ? (float*)g_y1 : Yext;

    // Weights: this thread's column, this CTA's k-slice -> 64 u64 in registers.
    u64 wreg[64];
#pragma unroll
    for (int i = 0; i < 64; i++)
        wreg[i] = Whg[(size_t)((int)rank * 64 + i) * H_ + tid];

    // init: zero parity-0 h (own 64 cols x 2 batches); arm both tx barriers
    if (tid < 128) (&hbuf[0][0][0])[tid] = 0ULL;
    if (tid == 0) {
        mbar_init(smem_u32(&mbars[0]), 1);
        mbar_init(smem_u32(&mbars[1]), 1);
        mbar_arrive_expect_tx(smem_u32(&mbars[0]), STEP_TX_BYTES);
        mbar_arrive_expect_tx(smem_u32(&mbars[1]), STEP_TX_BYTES);
    }
    __syncthreads();
    cluster_arrive();   // init/arm visible cluster-wide before any st.async
    cluster_wait();

    const uint32_t pb_addr = smem_u32(&pbuf[0][0][0][0]);
    const uint32_t dstP    = mapa_u32(pb_addr, (uint32_t)destRank);
    const uint32_t dstM[2] = { mapa_u32(smem_u32(&mbars[0]), (uint32_t)destRank),
                               mapa_u32(smem_u32(&mbars[1]), (uint32_t)destRank) };
    const uint32_t myM[2]  = { smem_u32(&mbars[0]), smem_u32(&mbars[1]) };

    // Epilogue task mapping: tid < 128 -> (batch bsel, own column tcol)
    const int  bsel   = (tid >> 6) & 1;
    const int  tcol   = tid & 63;
    const int  tjg    = (int)rank * 64 + tcol;      // global column (owned)
    const bool isTask = (tid < 128);
    const size_t zbT  = (size_t)(b0 + bsel) * T_ * H_ + tjg;

    float2 zt = make_float2(0.f, 0.f);
    if (isTask) zt = g_Z[zbT];             // prefetch z for t=0

    int phv[2] = { 0, 0 };                 // phase trackers

    for (int t = 0; t < T_; t++) {
        const int p = t & 1, q = p ^ 1;

        // ---- k-loop over OWN k-slice: local h only, no peer wait ----
        const u64* __restrict__ h0 = &hbuf[p][0][0];
        const u64* __restrict__ h1 = &hbuf[p][1][0];

        u64 a0e = 0, a0o = 0, a1e = 0, a1o = 0;
#pragma unroll
        for (int i = 0; i < 32; i++) {
            ulonglong2 ha = *(const ulonglong2*)(h0 + 2 * i);  // broadcast
            ulonglong2 hb = *(const ulonglong2*)(h1 + 2 * i);  // broadcast
            ffma2(a0e, ha.x, wreg[2 * i]);
            ffma2(a0o, ha.y, wreg[2 * i + 1]);
            ffma2(a1e, hb.x, wreg[2 * i]);
            ffma2(a1o, hb.y, wreg[2 * i + 1]);
        }
        u64 part0 = fadd2(a0e, a0o);   // {f,c} partial, batch 0
        u64 part1 = fadd2(a1e, a1o);   // {f,c} partial, batch 1

        // ---- fire partials to the column-owner CTA (HW-tracked tx) ----
        {
            uint32_t off = (uint32_t)((((p * 64 + lc) * 2 + 0) * 4 + (int)rank) * 8);
            st_async_u64(dstP + off,      part0, dstM[p]);
            st_async_u64(dstP + off + 32, part1, dstM[p]);   // batch stride = 4 u64
        }

        float hn = 0.f;
        if (isTask) {
            // wait: all 4096 bytes of this parity's partials have landed
            mbar_wait_cluster(myM[p], phv[p]);
            phv[p] ^= 1;
            if (tid == 0) mbar_arrive_expect_tx(myM[p], STEP_TX_BYTES);  // re-arm for t+2

            // reduce 4 source partials (2x LDS.128) + gates
            ulonglong2 pa = *(const ulonglong2*)&pbuf[p][tcol][bsel][0];
            ulonglong2 pb = *(const ulonglong2*)&pbuf[p][tcol][bsel][2];
            u64 s = fadd2(fadd2(pa.x, pa.y), fadd2(pb.x, pb.y));
            float af, ac;
            unpack2(s, af, ac);
            af += zt.x;
            ac += zt.y;

            float hold, dm;
            unpack2(hbuf[p][bsel][tcol], hold, dm);
            (void)dm;

            float f  = fmaf(0.5f, tanh_fast(0.5f * af), 0.5f);   // sigmoid
            float cg = tanh_fast(ac);
            hn = fmaf(f, hold - cg, cg);                         // f*h + (1-f)*c

            hbuf[q][bsel][tcol] = pack2(hn, hn);   // LOCAL store only!

            // overlap with global traffic
            Y[zbT + (size_t)t * H_] = hn;
            if (t < T_ - 1) zt = g_Z[zbT + (size_t)(t + 1) * H_];
            else            Hfin[(b0 + bsel) * H_ + tjg] = hn;
        }
        __syncthreads();   // h[q] written before anyone's next k-loop
    }

    // trailing rendezvous: all CTAs resident until final st.async land
    cluster_arrive();
    cluster_wait();
}

// ---------------------------------------------------------------------------
// Launch
// ---------------------------------------------------------------------------
extern "C" void kernel_launch(void* const* d_in, const int* in_sizes, int n_in,
                              void* d_out, int out_size)
{
    const float* x   = (const float*)d_in[0];
    const float* Wf1 = (const float*)d_in[1];
    const float* bf1 = (const float*)d_in[2];
    const float* Wc1 = (const float*)d_in[3];
    const float* bc1 = (const float*)d_in[4];
    const float* Wf2 = (const float*)d_in[5];
    const float* bf2 = (const float*)d_in[6];
    const float* Wc2 = (const float*)d_in[7];
    const float* bc2 = (const float*)d_in[8];

    float* out = (float*)d_out;
    float* y2  = out;                               // [B, T, H]
    float* h1  = out + (size_t)NT * H_;             // hidden[0]
    float* h2  = h1 + (size_t)B_ * H_;              // hidden[1]

    // weight repack (both layers)
    repack_wh<<<H_, H_>>>(Wf1, Wc1, I_, 0);
    repack_wh<<<H_, H_>>>(Wf2, Wc2, H_, 1);

    // layer 1
    gemm_x<<<dim3(NT / 128, H_ / 32), 256>>>(x, I_, 0, Wf1, Wc1, bf1, bc1);
    mgu_recur8<<<128, 256>>>(0, nullptr, h1);

    // layer 2 (reads g_y1)
    gemm_x<<<dim3(NT / 128, H_ / 32), 256>>>(nullptr, H_, 1, Wf2, Wc2, bf2, bc2);
    mgu_recur8<<<128, 256>>>(1, y2, h2);
}